// round 14
// baseline (speedup 1.0000x reference)
#include <cuda_runtime.h>
#include <math.h>
#include <string.h>

#define B_SZ      32
#define T_LEN     160000
#define HOPX      128
#define PADX      256
#define N_FRAMES  1251
#define N_BINS    257
#define N_FB      (B_SZ * N_FRAMES)
#define N_ROWS    (B_SZ * N_BINS)
#define TOTAL_OUT (B_SZ * N_FRAMES * N_BINS)

#define PI_F     3.14159265358979323846f
#define TWO_PI_F 6.28318530717958647692f
#define HSQT2_F  0.70710678118654752440f

__device__ float2 g_tw[256];          // (cos,sin)(2*pi*m/512), double->f32
__device__ float  g_win[512];         // window bits from HOST glibc cosf
__device__ float  g_phase[TOTAL_OUT];

__global__ void build_tw_kernel() {
    int i = blockIdx.x * blockDim.x + threadIdx.x;
    if (i < 256) {
        double s, c;
        sincospi((double)i / 256.0, &s, &c);
        g_tw[i] = make_float2((float)c, (float)s);
    }
}

// FFTPACK/pocketfft radf4, bit-faithful f32, NO fma. Layouts:
// CC(i,k,j)=cc[i+ido*(k+l1*j)], CH(i,j,k)=ch[i+ido*(j+4*k)].
__device__ __forceinline__ void radf4_stage(const float* cc, float* ch,
                                            int ido, int l1, int tid) {
    const int half = (ido - 2) / 2;          // #part2 units per k
    const int g = 2 + half;
    const int U = l1 * g;
    if (tid >= U) return;
    const int k = tid / g;
    const int p = tid % g;
#define CCX(i, kk, j) cc[(i) + ido * ((kk) + l1 * (j))]
#define CHX(i, j, kk) ch[(i) + ido * ((j) + 4 * (kk))]
    if (p == 0) {                            // part1 (fortran I=1)
        float a0 = CCX(0, k, 0), a1 = CCX(0, k, 1);
        float a2 = CCX(0, k, 2), a3 = CCX(0, k, 3);
        float tr1 = __fadd_rn(a1, a3);
        float tr2 = __fadd_rn(a0, a2);
        CHX(0, 0, k)       = __fadd_rn(tr1, tr2);
        CHX(ido - 1, 3, k) = __fsub_rn(tr2, tr1);
        CHX(ido - 1, 1, k) = __fsub_rn(a0, a2);
        CHX(0, 2, k)       = __fsub_rn(a3, a1);
    } else if (p <= half) {                  // part2, m = p (fortran I=2m+1)
        const int m  = p;
        const int ir = 2 * m - 1, ii = 2 * m;
        const int icr = ido - 2 * m - 1, ici = ido - 2 * m;
        float2 w1 = g_tw[l1 * m];
        float2 w2 = g_tw[2 * l1 * m];
        float2 w3 = g_tw[3 * l1 * m];
        float x1r = CCX(ir, k, 1), x1i = CCX(ii, k, 1);
        float x2r = CCX(ir, k, 2), x2i = CCX(ii, k, 2);
        float x3r = CCX(ir, k, 3), x3i = CCX(ii, k, 3);
        float cr2 = __fadd_rn(__fmul_rn(w1.x, x1r), __fmul_rn(w1.y, x1i));
        float ci2 = __fsub_rn(__fmul_rn(w1.x, x1i), __fmul_rn(w1.y, x1r));
        float cr3 = __fadd_rn(__fmul_rn(w2.x, x2r), __fmul_rn(w2.y, x2i));
        float ci3 = __fsub_rn(__fmul_rn(w2.x, x2i), __fmul_rn(w2.y, x2r));
        float cr4 = __fadd_rn(__fmul_rn(w3.x, x3r), __fmul_rn(w3.y, x3i));
        float ci4 = __fsub_rn(__fmul_rn(w3.x, x3i), __fmul_rn(w3.y, x3r));
        float tr1 = __fadd_rn(cr2, cr4), tr4 = __fsub_rn(cr4, cr2);
        float ti1 = __fadd_rn(ci2, ci4), ti4 = __fsub_rn(ci2, ci4);
        float ar = CCX(ir, k, 0), ai = CCX(ii, k, 0);
        float tr2 = __fadd_rn(ar, cr3), tr3 = __fsub_rn(ar, cr3);
        float ti2 = __fadd_rn(ai, ci3), ti3 = __fsub_rn(ai, ci3);
        CHX(ir, 0, k)  = __fadd_rn(tr1, tr2);
        CHX(icr, 3, k) = __fsub_rn(tr2, tr1);
        CHX(ii, 0, k)  = __fadd_rn(ti1, ti2);
        CHX(ici, 3, k) = __fsub_rn(ti1, ti2);
        CHX(ir, 2, k)  = __fadd_rn(ti4, tr3);
        CHX(icr, 1, k) = __fsub_rn(tr3, ti4);
        CHX(ii, 2, k)  = __fadd_rn(tr4, ti3);
        CHX(ici, 1, k) = __fsub_rn(tr4, ti3);
    } else {                                 // part3 (fortran I=IDO, ido even)
        const int i0 = ido - 1;
        float c1 = CCX(i0, k, 0), c2 = CCX(i0, k, 1);
        float c3 = CCX(i0, k, 2), c4 = CCX(i0, k, 3);
        float ti1 = __fmul_rn(-HSQT2_F, __fadd_rn(c2, c4));
        float tr1 = __fmul_rn(HSQT2_F, __fsub_rn(c2, c4));
        CHX(i0, 0, k) = __fadd_rn(tr1, c1);
        CHX(i0, 2, k) = __fsub_rn(c1, tr1);
        CHX(0, 1, k)  = __fsub_rn(ti1, c3);
        CHX(0, 3, k)  = __fadd_rn(ti1, c3);
    }
#undef CCX
#undef CHX
}

// One block = one frame: window -> pocketfft f32 rfft (radf4 x4, radf2) ->
// halfcomplex -> CR atan2 -> phase.
__global__ __launch_bounds__(128) void fft_phase_kernel(const float* __restrict__ wav) {
    __shared__ float A[512];
    __shared__ float B[512];
    const int fb    = blockIdx.x;
    const int frame = fb % N_FRAMES;
    const int b     = fb / N_FRAMES;
    const int tid   = threadIdx.x;

    const float* wv = wav + (size_t)b * T_LEN;
    const int base  = frame * HOPX - PADX;
    for (int t = tid; t < 512; t += 128) {
        int i0 = base + t;
        int j0 = (i0 < 0) ? -i0 : ((i0 >= T_LEN) ? 2 * (T_LEN - 1) - i0 : i0);
        A[t] = __fmul_rn(wv[j0], g_win[t]);
    }
    __syncthreads();

    // Stage 1: radf4 ido=1, l1=128 (no twiddles)  A->B
    {
        int k = tid;
        float x0 = A[k], x1 = A[k + 128], x2 = A[k + 256], x3 = A[k + 384];
        float tr1 = __fadd_rn(x1, x3);
        float tr2 = __fadd_rn(x0, x2);
        B[4 * k]     = __fadd_rn(tr1, tr2);
        B[4 * k + 3] = __fsub_rn(tr2, tr1);
        B[4 * k + 1] = __fsub_rn(x0, x2);
        B[4 * k + 2] = __fsub_rn(x3, x1);
    }
    __syncthreads();
    radf4_stage(B, A, 4, 32, tid);   __syncthreads();   // Stage 2
    radf4_stage(A, B, 16, 8, tid);   __syncthreads();   // Stage 3
    radf4_stage(B, A, 64, 2, tid);   __syncthreads();   // Stage 4
    // Stage 5: radf2 ido=256, l1=1  A->B
    if (tid == 0) {
        B[0]   = __fadd_rn(A[0], A[256]);
        B[511] = __fsub_rn(A[0], A[256]);
        B[256] = -A[511];
        B[255] = A[255];
    } else {
        const int m = tid;                     // 1..127, fortran I=2m+1
        float2 w = g_tw[m];
        float xr = A[2 * m - 1 + 256], xi = A[2 * m + 256];
        float tr2 = __fadd_rn(__fmul_rn(w.x, xr), __fmul_rn(w.y, xi));
        float ti2 = __fsub_rn(__fmul_rn(w.x, xi), __fmul_rn(w.y, xr));
        float ar = A[2 * m - 1], ai = A[2 * m];
        B[2 * m]       = __fadd_rn(ai, ti2);
        B[512 - 2 * m] = __fsub_rn(ti2, ai);
        B[2 * m - 1]   = __fadd_rn(ar, tr2);
        B[511 - 2 * m] = __fsub_rn(ar, tr2);
    }
    __syncthreads();

    // Halfcomplex -> phases: X[0]=(hc0,+0), X[k]=(hc[2k-1],hc[2k]), X[256]=(hc511,+0)
    for (int k = tid; k < N_BINS; k += 128) {
        double re, im;
        if (k == 0)        { re = (double)B[0];         im = 0.0; }
        else if (k == 256) { re = (double)B[511];       im = 0.0; }
        else               { re = (double)B[2 * k - 1]; im = (double)B[2 * k]; }
        g_phase[(size_t)fb * N_BINS + k] = (float)atan2(im, re);
    }
}

// f32-faithful unwrap + IF; cumsum via jax associative_scan pair tree.
__global__ __launch_bounds__(256) void unwrap_out_kernel(float* __restrict__ out) {
    const int row = blockIdx.x;
    const int b   = row / N_BINS;
    const int k   = row % N_BINS;
    const int tid = threadIdx.x;

    __shared__ float ph[N_FRAMES];
    __shared__ float sc[2495];

    const float* gp = g_phase + (size_t)b * N_FRAMES * N_BINS + k;
    for (int f = tid; f < N_FRAMES; f += 256)
        ph[f] = gp[(size_t)f * N_BINS];
    __syncthreads();

    for (int f = tid; f < N_FRAMES - 1; f += 256) {
        float dd = __fsub_rn(ph[f + 1], ph[f]);
        float s  = __fadd_rn(dd, PI_F);
        float t  = fmodf(s, TWO_PI_F);
        if (t < 0.0f) t = __fadd_rn(t, TWO_PI_F);
        float ddmod = __fsub_rn(t, PI_F);
        if (ddmod == -PI_F && dd > 0.0f) ddmod = PI_F;
        sc[f] = __fsub_rn(ddmod, dd);
    }
    __syncthreads();

    const int SZ[11] = {1250, 625, 312, 156, 78, 39, 19, 9, 4, 2, 1};
    const int OF[11] = {0, 1250, 1875, 2187, 2343, 2421, 2460, 2479, 2488, 2492, 2494};

#pragma unroll
    for (int l = 0; l < 10; ++l) {
        const int nOut = SZ[l + 1], oIn = OF[l], oOut = OF[l + 1];
        for (int i = tid; i < nOut; i += 256)
            sc[oOut + i] = __fadd_rn(sc[oIn + 2 * i], sc[oIn + 2 * i + 1]);
        __syncthreads();
    }
#pragma unroll
    for (int l = 9; l >= 0; --l) {
        const int nl = SZ[l], oIn = OF[l], oUp = OF[l + 1];
        for (int j = tid + 1; j < nl; j += 256) {
            if (j & 1) sc[oIn + j] = sc[oUp + (j >> 1)];
            else       sc[oIn + j] = __fadd_rn(sc[oUp + (j >> 1) - 1], sc[oIn + j]);
        }
        __syncthreads();
    }
    for (int f = tid; f < N_FRAMES; f += 256) {
        float u = (f == 0) ? ph[0] : __fadd_rn(ph[f], sc[f - 1]);
        ph[f] = u;
    }
    __syncthreads();

    float* op = out + (size_t)b * N_FRAMES * N_BINS + k;
    for (int f = tid; f < N_FRAMES; f += 256) {
        float vv = (f == 0) ? ph[0] : __fsub_rn(ph[f], ph[f - 1]);
        op[(size_t)f * N_BINS] = __fdiv_rn(vv, PI_F);
    }
}

// Window computed on HOST with the container's glibc cosf — the same libm
// XLA:CPU's scalarized cos op calls. Static buffer persists for graph replays.
static float h_win[512];

extern "C" void kernel_launch(void* const* d_in, const int* in_sizes, int n_in,
                              void* d_out, int out_size) {
    const float* wav = (const float*)d_in[0];
    float* out = (float*)d_out;
    (void)in_sizes; (void)n_in; (void)out_size;

    {
        const unsigned int two_pi_bits = 0x40C90FDBu;   // fl32(2*pi)
        float two_pi;
        memcpy(&two_pi, &two_pi_bits, 4);
        volatile int vi = 0;                 // defeat MPFR constant folding
        for (int n = 0; n < 512; ++n) {
            int i = vi;
            float a  = two_pi * (float)i;    // fl32(2pi_f32 * i)
            float th = a / 512.0f;           // exact
            float c  = cosf(th);             // glibc cosf bits
            h_win[n] = 0.5f - 0.5f * c;      // 0.5*c exact; one rounding
            vi = vi + 1;
        }
        cudaMemcpyToSymbolAsync(g_win, h_win, 512 * sizeof(float), 0,
                                cudaMemcpyHostToDevice, 0);
    }

    build_tw_kernel<<<1, 256>>>();
    fft_phase_kernel<<<N_FB, 128>>>(wav);
    unwrap_out_kernel<<<N_ROWS, 256>>>(out);
}

// round 15
// speedup vs baseline: 4.1634x; 4.1634x over previous
#include <cuda_runtime.h>
#include <math.h>
#include <string.h>

#define B_SZ      32
#define T_LEN     160000
#define HOPX      128
#define PADX      256
#define N_FRAMES  1251
#define N_BINS    257
#define N_FB      (B_SZ * N_FRAMES)
#define N_ROWS    (B_SZ * N_BINS)
#define TOTAL_OUT (B_SZ * N_FRAMES * N_BINS)

#define PI_F     3.14159265358979323846f
#define TWO_PI_F 6.28318530717958647692f
#define HSQT2_F  0.70710678118654752440f

__device__ float2 g_tw[256];          // (cos,sin)(2*pi*m/512), double->f32
__device__ float  g_win[512];         // window bits from HOST glibc cosf
__device__ float  g_phase[TOTAL_OUT];
__device__ float2 g_atan_tab[17];     // DF atan(i/16)
__device__ float2 g_base_tab[4];      // DF quadrant bases: 0, pi/2, pi, pi/2

__global__ void build_tables_kernel() {
    int i = threadIdx.x;
    if (i < 256) {
        double s, c;
        sincospi((double)i / 256.0, &s, &c);
        g_tw[i] = make_float2((float)c, (float)s);
    }
    if (i < 17) {
        double v = atan((double)i / 16.0);
        float hi = (float)v;
        g_atan_tab[i] = make_float2(hi, (float)(v - (double)hi));
    }
    if (i == 0) {
        double pi = 3.141592653589793238462643383279502884;
        double p2 = pi * 0.5;
        float pih = (float)pi, p2h = (float)p2;
        g_base_tab[0] = make_float2(0.0f, 0.0f);
        g_base_tab[1] = make_float2(p2h, (float)(p2 - (double)p2h));
        g_base_tab[2] = make_float2(pih, (float)(pi - (double)pih));
        g_base_tab[3] = make_float2(p2h, (float)(p2 - (double)p2h));
    }
}

// exact two-sum (all intrinsics: immune to fast-math)
__device__ __forceinline__ void tsum(float a, float b, float& s, float& e) {
    s = __fadd_rn(a, b);
    float bb = __fsub_rn(s, a);
    e = __fadd_rn(__fsub_rn(a, __fsub_rn(s, bb)), __fsub_rn(b, bb));
}

// double-float atan2 on the fp32 pipe; matches correctly-rounded f32 atan2
// to ~2^-35 (1-ulp deviations on ~1e-3 of elements; never flips signs).
__device__ float atan2_df(float y, float x) {
    float ay = fabsf(y), ax = fabsf(x);
    if (ay == 0.0f)
        return signbit(x) ? copysignf(PI_F, y) : copysignf(0.0f, y);
    bool sw = ay > ax;
    float nf = sw ? ax : ay;
    float df = sw ? ay : ax;
    // t = nf/df in DF (exact-remainder refinement)
    float q0 = __fdiv_rn(nf, df);
    float q1 = __fdiv_rn(fmaf(-q0, df, nf), df);
    int i = (int)rintf(__fmul_rn(q0, 16.0f));
    float a = (float)i * 0.0625f;                        // exact
    // num = t - a  (DF)
    float n0, ne; tsum(q0, -a, n0, ne);
    float n1 = __fadd_rn(ne, q1);
    // den = 1 + t*a  (DF)
    float p0 = __fmul_rn(q0, a);
    float p1 = __fadd_rn(fmaf(q0, a, -p0), __fmul_rn(q1, a));
    float d0, de; tsum(1.0f, p0, d0, de);
    float dl = __fadd_rn(de, p1);
    // u = num/den (DF), |u| <= 1/32
    float u0 = __fdiv_rn(n0, d0);
    float rh = fmaf(-u0, d0, n0);
    float rl = __fsub_rn(n1, __fmul_rn(u0, dl));
    float u1 = __fdiv_rn(__fadd_rn(rh, rl), d0);
    // atan(u) = u + u*p(u^2), p = -z/3 + z^2/5 - z^3/7
    float z = __fmul_rn(u0, u0);
    float p = __fmul_rn(z, __fadd_rn(-0.33333334f,
              __fmul_rn(z, __fadd_rn(0.2f, __fmul_rn(z, -0.14285715f)))));
    float corr = __fadd_rn(u1, __fmul_rn(u0, p));
    float2 T = g_atan_tab[i];
    float s0, e0; tsum(T.x, u0, s0, e0);
    float tl = __fadd_rn(__fadd_rn(e0, T.y), corr);      // atan(t)=s0+tl
    // cases: 0:x>=0,nosw:(0,+) 1:x>=0,sw:(pi/2,-) 2:x<0,nosw:(pi,-) 3:x<0,sw:(pi/2,+)
    int cse = (signbit(x) ? 2 : 0) | (sw ? 1 : 0);
    float2 Bc = g_base_tab[cse];
    float sgn = (cse == 1 || cse == 2) ? -1.0f : 1.0f;
    float f0, fe; tsum(Bc.x, __fmul_rn(sgn, s0), f0, fe);
    float fl = __fadd_rn(__fadd_rn(fe, Bc.y), __fmul_rn(sgn, tl));
    float r = __fadd_rn(f0, fl);
    return signbit(y) ? -r : r;
}

// FFTPACK/pocketfft radf4, bit-faithful f32, NO fma — identical op order to
// the passing R13 kernel; lanes of one warp loop over the independent units.
__device__ __forceinline__ void radf4_warp(const float* cc, float* ch,
                                           int ido, int l1, int lane) {
    const int half = (ido - 2) / 2;
    const int g = 2 + half;
    const int U = l1 * g;
#define CCX(i, kk, j) cc[(i) + ido * ((kk) + l1 * (j))]
#define CHX(i, j, kk) ch[(i) + ido * ((j) + 4 * (kk))]
    for (int u = lane; u < U; u += 32) {
        const int k = u / g;
        const int p = u % g;
        if (p == 0) {
            float a0 = CCX(0, k, 0), a1 = CCX(0, k, 1);
            float a2 = CCX(0, k, 2), a3 = CCX(0, k, 3);
            float tr1 = __fadd_rn(a1, a3);
            float tr2 = __fadd_rn(a0, a2);
            CHX(0, 0, k)       = __fadd_rn(tr1, tr2);
            CHX(ido - 1, 3, k) = __fsub_rn(tr2, tr1);
            CHX(ido - 1, 1, k) = __fsub_rn(a0, a2);
            CHX(0, 2, k)       = __fsub_rn(a3, a1);
        } else if (p <= half) {
            const int m  = p;
            const int ir = 2 * m - 1, ii = 2 * m;
            const int icr = ido - 2 * m - 1, ici = ido - 2 * m;
            float2 w1 = g_tw[l1 * m];
            float2 w2 = g_tw[2 * l1 * m];
            float2 w3 = g_tw[3 * l1 * m];
            float x1r = CCX(ir, k, 1), x1i = CCX(ii, k, 1);
            float x2r = CCX(ir, k, 2), x2i = CCX(ii, k, 2);
            float x3r = CCX(ir, k, 3), x3i = CCX(ii, k, 3);
            float cr2 = __fadd_rn(__fmul_rn(w1.x, x1r), __fmul_rn(w1.y, x1i));
            float ci2 = __fsub_rn(__fmul_rn(w1.x, x1i), __fmul_rn(w1.y, x1r));
            float cr3 = __fadd_rn(__fmul_rn(w2.x, x2r), __fmul_rn(w2.y, x2i));
            float ci3 = __fsub_rn(__fmul_rn(w2.x, x2i), __fmul_rn(w2.y, x2r));
            float cr4 = __fadd_rn(__fmul_rn(w3.x, x3r), __fmul_rn(w3.y, x3i));
            float ci4 = __fsub_rn(__fmul_rn(w3.x, x3i), __fmul_rn(w3.y, x3r));
            float tr1 = __fadd_rn(cr2, cr4), tr4 = __fsub_rn(cr4, cr2);
            float ti1 = __fadd_rn(ci2, ci4), ti4 = __fsub_rn(ci2, ci4);
            float ar = CCX(ir, k, 0), ai = CCX(ii, k, 0);
            float tr2 = __fadd_rn(ar, cr3), tr3 = __fsub_rn(ar, cr3);
            float ti2 = __fadd_rn(ai, ci3), ti3 = __fsub_rn(ai, ci3);
            CHX(ir, 0, k)  = __fadd_rn(tr1, tr2);
            CHX(icr, 3, k) = __fsub_rn(tr2, tr1);
            CHX(ii, 0, k)  = __fadd_rn(ti1, ti2);
            CHX(ici, 3, k) = __fsub_rn(ti1, ti2);
            CHX(ir, 2, k)  = __fadd_rn(ti4, tr3);
            CHX(icr, 1, k) = __fsub_rn(tr3, ti4);
            CHX(ii, 2, k)  = __fadd_rn(tr4, ti3);
            CHX(ici, 1, k) = __fsub_rn(tr4, ti3);
        } else {
            const int i0 = ido - 1;
            float c1 = CCX(i0, k, 0), c2 = CCX(i0, k, 1);
            float c3 = CCX(i0, k, 2), c4 = CCX(i0, k, 3);
            float ti1 = __fmul_rn(-HSQT2_F, __fadd_rn(c2, c4));
            float tr1 = __fmul_rn(HSQT2_F, __fsub_rn(c2, c4));
            CHX(i0, 0, k) = __fadd_rn(tr1, c1);
            CHX(i0, 2, k) = __fsub_rn(c1, tr1);
            CHX(0, 1, k)  = __fsub_rn(ti1, c3);
            CHX(0, 3, k)  = __fadd_rn(ti1, c3);
        }
    }
#undef CCX
#undef CHX
}

// 8 frames per block, one warp per frame; __syncwarp between stages.
__global__ __launch_bounds__(256) void fft_phase_kernel(const float* __restrict__ wav) {
    __shared__ float SA[8][512];
    __shared__ float SB[8][512];
    const int warp = threadIdx.x >> 5;
    const int lane = threadIdx.x & 31;
    const int fb   = blockIdx.x * 8 + warp;       // 5004*8 == 40032 exactly
    const int frame = fb % N_FRAMES;
    const int b     = fb / N_FRAMES;
    float* A = SA[warp];
    float* B = SB[warp];

    const float* wv = wav + (size_t)b * T_LEN;
    const int base  = frame * HOPX - PADX;
    for (int t = lane; t < 512; t += 32) {
        int i0 = base + t;
        int j0 = (i0 < 0) ? -i0 : ((i0 >= T_LEN) ? 2 * (T_LEN - 1) - i0 : i0);
        A[t] = __fmul_rn(wv[j0], g_win[t]);
    }
    __syncwarp();

    // Stage 1: radf4 ido=1, l1=128  A->B
    for (int k = lane; k < 128; k += 32) {
        float x0 = A[k], x1 = A[k + 128], x2 = A[k + 256], x3 = A[k + 384];
        float tr1 = __fadd_rn(x1, x3);
        float tr2 = __fadd_rn(x0, x2);
        B[4 * k]     = __fadd_rn(tr1, tr2);
        B[4 * k + 3] = __fsub_rn(tr2, tr1);
        B[4 * k + 1] = __fsub_rn(x0, x2);
        B[4 * k + 2] = __fsub_rn(x3, x1);
    }
    __syncwarp();
    radf4_warp(B, A, 4, 32, lane);  __syncwarp();
    radf4_warp(A, B, 16, 8, lane);  __syncwarp();
    radf4_warp(B, A, 64, 2, lane);  __syncwarp();
    // Stage 5: radf2 ido=256, l1=1  A->B
    for (int m = lane; m < 128; m += 32) {
        if (m == 0) {
            B[0]   = __fadd_rn(A[0], A[256]);
            B[511] = __fsub_rn(A[0], A[256]);
            B[256] = -A[511];
            B[255] = A[255];
        } else {
            float2 w = g_tw[m];
            float xr = A[2 * m - 1 + 256], xi = A[2 * m + 256];
            float tr2 = __fadd_rn(__fmul_rn(w.x, xr), __fmul_rn(w.y, xi));
            float ti2 = __fsub_rn(__fmul_rn(w.x, xi), __fmul_rn(w.y, xr));
            float ar = A[2 * m - 1], ai = A[2 * m];
            B[2 * m]       = __fadd_rn(ai, ti2);
            B[512 - 2 * m] = __fsub_rn(ti2, ai);
            B[2 * m - 1]   = __fadd_rn(ar, tr2);
            B[511 - 2 * m] = __fsub_rn(ar, tr2);
        }
    }
    __syncwarp();

    for (int k = lane; k < N_BINS; k += 32) {
        float re, im;
        if (k == 0)        { re = B[0];         im = 0.0f; }
        else if (k == 256) { re = B[511];       im = 0.0f; }
        else               { re = B[2 * k - 1]; im = B[2 * k]; }
        g_phase[(size_t)fb * N_BINS + k] = atan2_df(im, re);
    }
}

// f32-faithful unwrap + IF; cumsum via jax associative_scan pair tree.
__global__ __launch_bounds__(256) void unwrap_out_kernel(float* __restrict__ out) {
    const int row = blockIdx.x;
    const int b   = row / N_BINS;
    const int k   = row % N_BINS;
    const int tid = threadIdx.x;

    __shared__ float ph[N_FRAMES];
    __shared__ float sc[2495];

    const float* gp = g_phase + (size_t)b * N_FRAMES * N_BINS + k;
    for (int f = tid; f < N_FRAMES; f += 256)
        ph[f] = gp[(size_t)f * N_BINS];
    __syncthreads();

    for (int f = tid; f < N_FRAMES - 1; f += 256) {
        float dd = __fsub_rn(ph[f + 1], ph[f]);
        float s  = __fadd_rn(dd, PI_F);
        float t  = fmodf(s, TWO_PI_F);
        if (t < 0.0f) t = __fadd_rn(t, TWO_PI_F);
        float ddmod = __fsub_rn(t, PI_F);
        if (ddmod == -PI_F && dd > 0.0f) ddmod = PI_F;
        sc[f] = __fsub_rn(ddmod, dd);
    }
    __syncthreads();

    const int SZ[11] = {1250, 625, 312, 156, 78, 39, 19, 9, 4, 2, 1};
    const int OF[11] = {0, 1250, 1875, 2187, 2343, 2421, 2460, 2479, 2488, 2492, 2494};

#pragma unroll
    for (int l = 0; l < 10; ++l) {
        const int nOut = SZ[l + 1], oIn = OF[l], oOut = OF[l + 1];
        for (int i = tid; i < nOut; i += 256)
            sc[oOut + i] = __fadd_rn(sc[oIn + 2 * i], sc[oIn + 2 * i + 1]);
        __syncthreads();
    }
#pragma unroll
    for (int l = 9; l >= 0; --l) {
        const int nl = SZ[l], oIn = OF[l], oUp = OF[l + 1];
        for (int j = tid + 1; j < nl; j += 256) {
            if (j & 1) sc[oIn + j] = sc[oUp + (j >> 1)];
            else       sc[oIn + j] = __fadd_rn(sc[oUp + (j >> 1) - 1], sc[oIn + j]);
        }
        __syncthreads();
    }
    for (int f = tid; f < N_FRAMES; f += 256) {
        float u = (f == 0) ? ph[0] : __fadd_rn(ph[f], sc[f - 1]);
        ph[f] = u;
    }
    __syncthreads();

    float* op = out + (size_t)b * N_FRAMES * N_BINS + k;
    for (int f = tid; f < N_FRAMES; f += 256) {
        float vv = (f == 0) ? ph[0] : __fsub_rn(ph[f], ph[f - 1]);
        op[(size_t)f * N_BINS] = __fdiv_rn(vv, PI_F);
    }
}

// Window from HOST glibc cosf (the libm XLA:CPU called). Static: graph-safe.
static float h_win[512];

extern "C" void kernel_launch(void* const* d_in, const int* in_sizes, int n_in,
                              void* d_out, int out_size) {
    const float* wav = (const float*)d_in[0];
    float* out = (float*)d_out;
    (void)in_sizes; (void)n_in; (void)out_size;

    {
        const unsigned int two_pi_bits = 0x40C90FDBu;
        float two_pi;
        memcpy(&two_pi, &two_pi_bits, 4);
        volatile int vi = 0;                 // defeat MPFR constant folding
        for (int n = 0; n < 512; ++n) {
            int i = vi;
            float a  = two_pi * (float)i;
            float th = a / 512.0f;
            float c  = cosf(th);
            h_win[n] = 0.5f - 0.5f * c;
            vi = vi + 1;
        }
        cudaMemcpyToSymbolAsync(g_win, h_win, 512 * sizeof(float), 0,
                                cudaMemcpyHostToDevice, 0);
    }

    build_tables_kernel<<<1, 256>>>();
    fft_phase_kernel<<<N_FB / 8, 256>>>(wav);
    unwrap_out_kernel<<<N_ROWS, 256>>>(out);
}

// round 16
// speedup vs baseline: 5.5616x; 1.3358x over previous
#include <cuda_runtime.h>
#include <math.h>
#include <string.h>

#define B_SZ      32
#define T_LEN     160000
#define HOPX      128
#define PADX      256
#define N_FRAMES  1251
#define N_BINS    257
#define N_FB      (B_SZ * N_FRAMES)
#define TOTAL_OUT (B_SZ * N_FRAMES * N_BINS)

#define PI_F     3.14159265358979323846f
#define TWO_PI_F 6.28318530717958647692f
#define HSQT2_F  0.70710678118654752440f

__device__ float2 g_tw[256];          // (cos,sin)(2*pi*m/512), double->f32
__device__ float  g_win[512];         // window bits from HOST glibc cosf
__device__ float  g_phase[TOTAL_OUT];
__device__ float2 g_atan_tab[17];     // DF atan(i/16)
__device__ float2 g_base_tab[4];      // DF quadrant bases

__global__ void build_tables_kernel() {
    int i = threadIdx.x;
    if (i < 256) {
        double s, c;
        sincospi((double)i / 256.0, &s, &c);
        g_tw[i] = make_float2((float)c, (float)s);
    }
    if (i < 17) {
        double v = atan((double)i / 16.0);
        float hi = (float)v;
        g_atan_tab[i] = make_float2(hi, (float)(v - (double)hi));
    }
    if (i == 0) {
        double pi = 3.141592653589793238462643383279502884;
        double p2 = pi * 0.5;
        float pih = (float)pi, p2h = (float)p2;
        g_base_tab[0] = make_float2(0.0f, 0.0f);
        g_base_tab[1] = make_float2(p2h, (float)(p2 - (double)p2h));
        g_base_tab[2] = make_float2(pih, (float)(pi - (double)pih));
        g_base_tab[3] = make_float2(p2h, (float)(p2 - (double)p2h));
    }
}

// exact two-sum (intrinsics: immune to fast-math)
__device__ __forceinline__ void tsum(float a, float b, float& s, float& e) {
    s = __fadd_rn(a, b);
    float bb = __fsub_rn(s, a);
    e = __fadd_rn(__fsub_rn(a, __fsub_rn(s, bb)), __fsub_rn(b, bb));
}

// double-float atan2 on the fp32 pipe (~2^-35 accuracy).
__device__ float atan2_df(float y, float x) {
    float ay = fabsf(y), ax = fabsf(x);
    if (ay == 0.0f)
        return signbit(x) ? copysignf(PI_F, y) : copysignf(0.0f, y);
    bool sw = ay > ax;
    float nf = sw ? ax : ay;
    float df = sw ? ay : ax;
    float q0 = __fdiv_rn(nf, df);
    float q1 = __fdiv_rn(fmaf(-q0, df, nf), df);
    int i = (int)rintf(__fmul_rn(q0, 16.0f));
    float a = (float)i * 0.0625f;
    float n0, ne; tsum(q0, -a, n0, ne);
    float n1 = __fadd_rn(ne, q1);
    float p0 = __fmul_rn(q0, a);
    float p1 = __fadd_rn(fmaf(q0, a, -p0), __fmul_rn(q1, a));
    float d0, de; tsum(1.0f, p0, d0, de);
    float dl = __fadd_rn(de, p1);
    float u0 = __fdiv_rn(n0, d0);
    float rh = fmaf(-u0, d0, n0);
    float rl = __fsub_rn(n1, __fmul_rn(u0, dl));
    float u1 = __fdiv_rn(__fadd_rn(rh, rl), d0);
    float z = __fmul_rn(u0, u0);
    float p = __fmul_rn(z, __fadd_rn(-0.33333334f,
              __fmul_rn(z, __fadd_rn(0.2f, __fmul_rn(z, -0.14285715f)))));
    float corr = __fadd_rn(u1, __fmul_rn(u0, p));
    float2 T = g_atan_tab[i];
    float s0, e0; tsum(T.x, u0, s0, e0);
    float tl = __fadd_rn(__fadd_rn(e0, T.y), corr);
    int cse = (signbit(x) ? 2 : 0) | (sw ? 1 : 0);
    float2 Bc = g_base_tab[cse];
    float sgn = (cse == 1 || cse == 2) ? -1.0f : 1.0f;
    float f0, fe; tsum(Bc.x, __fmul_rn(sgn, s0), f0, fe);
    float fl = __fadd_rn(__fadd_rn(fe, Bc.y), __fmul_rn(sgn, tl));
    float r = __fadd_rn(f0, fl);
    return signbit(y) ? -r : r;
}

// FFTPACK/pocketfft radf4, bit-faithful f32, NO fma.
__device__ __forceinline__ void radf4_warp(const float* cc, float* ch,
                                           int ido, int l1, int lane) {
    const int half = (ido - 2) / 2;
    const int g = 2 + half;
    const int U = l1 * g;
#define CCX(i, kk, j) cc[(i) + ido * ((kk) + l1 * (j))]
#define CHX(i, j, kk) ch[(i) + ido * ((j) + 4 * (kk))]
    for (int u = lane; u < U; u += 32) {
        const int k = u / g;
        const int p = u % g;
        if (p == 0) {
            float a0 = CCX(0, k, 0), a1 = CCX(0, k, 1);
            float a2 = CCX(0, k, 2), a3 = CCX(0, k, 3);
            float tr1 = __fadd_rn(a1, a3);
            float tr2 = __fadd_rn(a0, a2);
            CHX(0, 0, k)       = __fadd_rn(tr1, tr2);
            CHX(ido - 1, 3, k) = __fsub_rn(tr2, tr1);
            CHX(ido - 1, 1, k) = __fsub_rn(a0, a2);
            CHX(0, 2, k)       = __fsub_rn(a3, a1);
        } else if (p <= half) {
            const int m  = p;
            const int ir = 2 * m - 1, ii = 2 * m;
            const int icr = ido - 2 * m - 1, ici = ido - 2 * m;
            float2 w1 = g_tw[l1 * m];
            float2 w2 = g_tw[2 * l1 * m];
            float2 w3 = g_tw[3 * l1 * m];
            float x1r = CCX(ir, k, 1), x1i = CCX(ii, k, 1);
            float x2r = CCX(ir, k, 2), x2i = CCX(ii, k, 2);
            float x3r = CCX(ir, k, 3), x3i = CCX(ii, k, 3);
            float cr2 = __fadd_rn(__fmul_rn(w1.x, x1r), __fmul_rn(w1.y, x1i));
            float ci2 = __fsub_rn(__fmul_rn(w1.x, x1i), __fmul_rn(w1.y, x1r));
            float cr3 = __fadd_rn(__fmul_rn(w2.x, x2r), __fmul_rn(w2.y, x2i));
            float ci3 = __fsub_rn(__fmul_rn(w2.x, x2i), __fmul_rn(w2.y, x2r));
            float cr4 = __fadd_rn(__fmul_rn(w3.x, x3r), __fmul_rn(w3.y, x3i));
            float ci4 = __fsub_rn(__fmul_rn(w3.x, x3i), __fmul_rn(w3.y, x3r));
            float tr1 = __fadd_rn(cr2, cr4), tr4 = __fsub_rn(cr4, cr2);
            float ti1 = __fadd_rn(ci2, ci4), ti4 = __fsub_rn(ci2, ci4);
            float ar = CCX(ir, k, 0), ai = CCX(ii, k, 0);
            float tr2 = __fadd_rn(ar, cr3), tr3 = __fsub_rn(ar, cr3);
            float ti2 = __fadd_rn(ai, ci3), ti3 = __fsub_rn(ai, ci3);
            CHX(ir, 0, k)  = __fadd_rn(tr1, tr2);
            CHX(icr, 3, k) = __fsub_rn(tr2, tr1);
            CHX(ii, 0, k)  = __fadd_rn(ti1, ti2);
            CHX(ici, 3, k) = __fsub_rn(ti1, ti2);
            CHX(ir, 2, k)  = __fadd_rn(ti4, tr3);
            CHX(icr, 1, k) = __fsub_rn(tr3, ti4);
            CHX(ii, 2, k)  = __fadd_rn(tr4, ti3);
            CHX(ici, 1, k) = __fsub_rn(tr4, ti3);
        } else {
            const int i0 = ido - 1;
            float c1 = CCX(i0, k, 0), c2 = CCX(i0, k, 1);
            float c3 = CCX(i0, k, 2), c4 = CCX(i0, k, 3);
            float ti1 = __fmul_rn(-HSQT2_F, __fadd_rn(c2, c4));
            float tr1 = __fmul_rn(HSQT2_F, __fsub_rn(c2, c4));
            CHX(i0, 0, k) = __fadd_rn(tr1, c1);
            CHX(i0, 2, k) = __fsub_rn(c1, tr1);
            CHX(0, 1, k)  = __fsub_rn(ti1, c3);
            CHX(0, 3, k)  = __fadd_rn(ti1, c3);
        }
    }
#undef CCX
#undef CHX
}

// 8 frames per block, one warp per frame; __syncwarp between stages.
__global__ __launch_bounds__(256) void fft_phase_kernel(const float* __restrict__ wav) {
    __shared__ float SA[8][512];
    __shared__ float SB[8][512];
    const int warp = threadIdx.x >> 5;
    const int lane = threadIdx.x & 31;
    const int fb   = blockIdx.x * 8 + warp;
    const int frame = fb % N_FRAMES;
    const int b     = fb / N_FRAMES;
    float* A = SA[warp];
    float* B = SB[warp];

    const float* wv = wav + (size_t)b * T_LEN;
    const int base  = frame * HOPX - PADX;
    for (int t = lane; t < 512; t += 32) {
        int i0 = base + t;
        int j0 = (i0 < 0) ? -i0 : ((i0 >= T_LEN) ? 2 * (T_LEN - 1) - i0 : i0);
        A[t] = __fmul_rn(wv[j0], g_win[t]);
    }
    __syncwarp();

    for (int k = lane; k < 128; k += 32) {
        float x0 = A[k], x1 = A[k + 128], x2 = A[k + 256], x3 = A[k + 384];
        float tr1 = __fadd_rn(x1, x3);
        float tr2 = __fadd_rn(x0, x2);
        B[4 * k]     = __fadd_rn(tr1, tr2);
        B[4 * k + 3] = __fsub_rn(tr2, tr1);
        B[4 * k + 1] = __fsub_rn(x0, x2);
        B[4 * k + 2] = __fsub_rn(x3, x1);
    }
    __syncwarp();
    radf4_warp(B, A, 4, 32, lane);  __syncwarp();
    radf4_warp(A, B, 16, 8, lane);  __syncwarp();
    radf4_warp(B, A, 64, 2, lane);  __syncwarp();
    for (int m = lane; m < 128; m += 32) {
        if (m == 0) {
            B[0]   = __fadd_rn(A[0], A[256]);
            B[511] = __fsub_rn(A[0], A[256]);
            B[256] = -A[511];
            B[255] = A[255];
        } else {
            float2 w = g_tw[m];
            float xr = A[2 * m - 1 + 256], xi = A[2 * m + 256];
            float tr2 = __fadd_rn(__fmul_rn(w.x, xr), __fmul_rn(w.y, xi));
            float ti2 = __fsub_rn(__fmul_rn(w.x, xi), __fmul_rn(w.y, xr));
            float ar = A[2 * m - 1], ai = A[2 * m];
            B[2 * m]       = __fadd_rn(ai, ti2);
            B[512 - 2 * m] = __fsub_rn(ti2, ai);
            B[2 * m - 1]   = __fadd_rn(ar, tr2);
            B[511 - 2 * m] = __fsub_rn(ar, tr2);
        }
    }
    __syncwarp();

    for (int k = lane; k < N_BINS; k += 32) {
        float re, im;
        if (k == 0)        { re = B[0];         im = 0.0f; }
        else if (k == 256) { re = B[511];       im = 0.0f; }
        else               { re = B[2 * k - 1]; im = B[2 * k]; }
        g_phase[(size_t)fb * N_BINS + k] = atan2_df(im, re);
    }
}

// Elementwise IF output. With phases bit-matching the reference, the ref's
// unwrap+cumsum+diff chain equals plain ddmod up to accumulated-rounding
// noise ~ulp(|cumsum|) ~ 1e-5 rad (rel contribution ~5e-6). Coalesced.
__global__ __launch_bounds__(256) void if_out_kernel(float* __restrict__ out) {
    int i = blockIdx.x * blockDim.x + threadIdx.x;
    if (i >= TOTAL_OUT) return;
    int rem = i % (N_FRAMES * N_BINS);
    float ph = g_phase[i];
    float o;
    if (rem < N_BINS) {                          // f == 0
        o = ph;
    } else {
        float dd = __fsub_rn(ph, g_phase[i - N_BINS]);
        float s  = __fadd_rn(dd, PI_F);
        float t  = fmodf(s, TWO_PI_F);
        if (t < 0.0f) t = __fadd_rn(t, TWO_PI_F);
        float ddmod = __fsub_rn(t, PI_F);
        if (ddmod == -PI_F && dd > 0.0f) ddmod = PI_F;
        o = ddmod;
    }
    out[i] = __fdiv_rn(o, PI_F);
}

// Window from HOST glibc cosf (the libm XLA:CPU called). Static: graph-safe.
static float h_win[512];

extern "C" void kernel_launch(void* const* d_in, const int* in_sizes, int n_in,
                              void* d_out, int out_size) {
    const float* wav = (const float*)d_in[0];
    float* out = (float*)d_out;
    (void)in_sizes; (void)n_in; (void)out_size;

    {
        const unsigned int two_pi_bits = 0x40C90FDBu;
        float two_pi;
        memcpy(&two_pi, &two_pi_bits, 4);
        volatile int vi = 0;                 // defeat MPFR constant folding
        for (int n = 0; n < 512; ++n) {
            int i = vi;
            float a  = two_pi * (float)i;
            float th = a / 512.0f;
            float c  = cosf(th);
            h_win[n] = 0.5f - 0.5f * c;
            vi = vi + 1;
        }
        cudaMemcpyToSymbolAsync(g_win, h_win, 512 * sizeof(float), 0,
                                cudaMemcpyHostToDevice, 0);
    }

    build_tables_kernel<<<1, 256>>>();
    fft_phase_kernel<<<N_FB / 8, 256>>>(wav);
    if_out_kernel<<<(TOTAL_OUT + 255) / 256, 256>>>(out);
}

// round 17
// speedup vs baseline: 6.1605x; 1.1077x over previous
#include <cuda_runtime.h>
#include <math.h>
#include <string.h>

#define B_SZ      32
#define T_LEN     160000
#define HOPX      128
#define PADX      256
#define N_FRAMES  1251
#define N_BINS    257
#define N_FB      (B_SZ * N_FRAMES)
#define TOTAL_OUT (B_SZ * N_FRAMES * N_BINS)

#define PI_F     3.14159265358979323846f
#define TWO_PI_F 6.28318530717958647692f
#define HSQT2_F  0.70710678118654752440f

__device__ float2 g_tw[256];          // (cos,sin)(2*pi*m/512), double->f32
__device__ float  g_win[512];         // window bits from HOST glibc cosf
__device__ float  g_phase[TOTAL_OUT]; // only block-boundary frames are written
__device__ float2 g_atan_tab[17];     // DF atan(i/16)
__device__ float2 g_base_tab[4];      // DF quadrant bases

__global__ void build_tables_kernel() {
    int i = threadIdx.x;
    if (i < 256) {
        double s, c;
        sincospi((double)i / 256.0, &s, &c);
        g_tw[i] = make_float2((float)c, (float)s);
    }
    if (i < 17) {
        double v = atan((double)i / 16.0);
        float hi = (float)v;
        g_atan_tab[i] = make_float2(hi, (float)(v - (double)hi));
    }
    if (i == 0) {
        double pi = 3.141592653589793238462643383279502884;
        double p2 = pi * 0.5;
        float pih = (float)pi, p2h = (float)p2;
        g_base_tab[0] = make_float2(0.0f, 0.0f);
        g_base_tab[1] = make_float2(p2h, (float)(p2 - (double)p2h));
        g_base_tab[2] = make_float2(pih, (float)(pi - (double)pih));
        g_base_tab[3] = make_float2(p2h, (float)(p2 - (double)p2h));
    }
}

// exact two-sum (intrinsics: immune to fast-math)
__device__ __forceinline__ void tsum(float a, float b, float& s, float& e) {
    s = __fadd_rn(a, b);
    float bb = __fsub_rn(s, a);
    e = __fadd_rn(__fsub_rn(a, __fsub_rn(s, bb)), __fsub_rn(b, bb));
}

// double-float atan2 on the fp32 pipe (~2^-33), divisions via RCP+Newton.
__device__ float atan2_df(float y, float x) {
    float ay = fabsf(y), ax = fabsf(x);
    if (ay == 0.0f)
        return signbit(x) ? copysignf(PI_F, y) : copysignf(0.0f, y);
    bool sw = ay > ax;
    float nf = sw ? ax : ay;
    float df = sw ? ay : ax;
    // t = nf/df in DF: reciprocal + Newton, residual-corrected low part
    float r = __frcp_rn(df);
    r = fmaf(fmaf(-df, r, 1.0f), r, r);
    float q0 = __fmul_rn(nf, r);
    float q1 = __fmul_rn(fmaf(-q0, df, nf), r);
    int i = (int)rintf(__fmul_rn(q0, 16.0f));
    float a = (float)i * 0.0625f;                        // exact
    float n0, ne; tsum(q0, -a, n0, ne);
    float n1 = __fadd_rn(ne, q1);
    float p0 = __fmul_rn(q0, a);
    float p1 = __fadd_rn(fmaf(q0, a, -p0), __fmul_rn(q1, a));
    float d0, de; tsum(1.0f, p0, d0, de);
    float dl = __fadd_rn(de, p1);
    // u = num/den in DF via reciprocal
    float rd = __frcp_rn(d0);
    rd = fmaf(fmaf(-d0, rd, 1.0f), rd, rd);
    float u0 = __fmul_rn(n0, rd);
    float rh = fmaf(-u0, d0, n0);
    float rl = __fsub_rn(n1, __fmul_rn(u0, dl));
    float u1 = __fmul_rn(__fadd_rn(rh, rl), rd);
    // atan(u) = u + u*p(u^2)
    float z = __fmul_rn(u0, u0);
    float p = __fmul_rn(z, __fadd_rn(-0.33333334f,
              __fmul_rn(z, __fadd_rn(0.2f, __fmul_rn(z, -0.14285715f)))));
    float corr = __fadd_rn(u1, __fmul_rn(u0, p));
    float2 T = g_atan_tab[i];
    float s0, e0; tsum(T.x, u0, s0, e0);
    float tl = __fadd_rn(__fadd_rn(e0, T.y), corr);
    int cse = (signbit(x) ? 2 : 0) | (sw ? 1 : 0);
    float2 Bc = g_base_tab[cse];
    float sgn = (cse == 1 || cse == 2) ? -1.0f : 1.0f;
    float f0, fe; tsum(Bc.x, __fmul_rn(sgn, s0), f0, fe);
    float fl = __fadd_rn(__fadd_rn(fe, Bc.y), __fmul_rn(sgn, tl));
    float rr = __fadd_rn(f0, fl);
    return signbit(y) ? -rr : rr;
}

// ddmod(dd) per the reference's f32 arithmetic
__device__ __forceinline__ float ddmod_of(float dd) {
    float s = __fadd_rn(dd, PI_F);
    float t = fmodf(s, TWO_PI_F);
    if (t < 0.0f) t = __fadd_rn(t, TWO_PI_F);
    float dm = __fsub_rn(t, PI_F);
    if (dm == -PI_F && dd > 0.0f) dm = PI_F;
    return dm;
}

// FFTPACK/pocketfft radf4, bit-faithful f32, NO fma.
__device__ __forceinline__ void radf4_warp(const float* cc, float* ch,
                                           int ido, int l1, int lane) {
    const int half = (ido - 2) / 2;
    const int g = 2 + half;
    const int U = l1 * g;
#define CCX(i, kk, j) cc[(i) + ido * ((kk) + l1 * (j))]
#define CHX(i, j, kk) ch[(i) + ido * ((j) + 4 * (kk))]
    for (int u = lane; u < U; u += 32) {
        const int k = u / g;
        const int p = u % g;
        if (p == 0) {
            float a0 = CCX(0, k, 0), a1 = CCX(0, k, 1);
            float a2 = CCX(0, k, 2), a3 = CCX(0, k, 3);
            float tr1 = __fadd_rn(a1, a3);
            float tr2 = __fadd_rn(a0, a2);
            CHX(0, 0, k)       = __fadd_rn(tr1, tr2);
            CHX(ido - 1, 3, k) = __fsub_rn(tr2, tr1);
            CHX(ido - 1, 1, k) = __fsub_rn(a0, a2);
            CHX(0, 2, k)       = __fsub_rn(a3, a1);
        } else if (p <= half) {
            const int m  = p;
            const int ir = 2 * m - 1, ii = 2 * m;
            const int icr = ido - 2 * m - 1, ici = ido - 2 * m;
            float2 w1 = g_tw[l1 * m];
            float2 w2 = g_tw[2 * l1 * m];
            float2 w3 = g_tw[3 * l1 * m];
            float x1r = CCX(ir, k, 1), x1i = CCX(ii, k, 1);
            float x2r = CCX(ir, k, 2), x2i = CCX(ii, k, 2);
            float x3r = CCX(ir, k, 3), x3i = CCX(ii, k, 3);
            float cr2 = __fadd_rn(__fmul_rn(w1.x, x1r), __fmul_rn(w1.y, x1i));
            float ci2 = __fsub_rn(__fmul_rn(w1.x, x1i), __fmul_rn(w1.y, x1r));
            float cr3 = __fadd_rn(__fmul_rn(w2.x, x2r), __fmul_rn(w2.y, x2i));
            float ci3 = __fsub_rn(__fmul_rn(w2.x, x2i), __fmul_rn(w2.y, x2r));
            float cr4 = __fadd_rn(__fmul_rn(w3.x, x3r), __fmul_rn(w3.y, x3i));
            float ci4 = __fsub_rn(__fmul_rn(w3.x, x3i), __fmul_rn(w3.y, x3r));
            float tr1 = __fadd_rn(cr2, cr4), tr4 = __fsub_rn(cr4, cr2);
            float ti1 = __fadd_rn(ci2, ci4), ti4 = __fsub_rn(ci2, ci4);
            float ar = CCX(ir, k, 0), ai = CCX(ii, k, 0);
            float tr2 = __fadd_rn(ar, cr3), tr3 = __fsub_rn(ar, cr3);
            float ti2 = __fadd_rn(ai, ci3), ti3 = __fsub_rn(ai, ci3);
            CHX(ir, 0, k)  = __fadd_rn(tr1, tr2);
            CHX(icr, 3, k) = __fsub_rn(tr2, tr1);
            CHX(ii, 0, k)  = __fadd_rn(ti1, ti2);
            CHX(ici, 3, k) = __fsub_rn(ti1, ti2);
            CHX(ir, 2, k)  = __fadd_rn(ti4, tr3);
            CHX(icr, 1, k) = __fsub_rn(tr3, ti4);
            CHX(ii, 2, k)  = __fadd_rn(tr4, ti3);
            CHX(ici, 1, k) = __fsub_rn(tr4, ti3);
        } else {
            const int i0 = ido - 1;
            float c1 = CCX(i0, k, 0), c2 = CCX(i0, k, 1);
            float c3 = CCX(i0, k, 2), c4 = CCX(i0, k, 3);
            float ti1 = __fmul_rn(-HSQT2_F, __fadd_rn(c2, c4));
            float tr1 = __fmul_rn(HSQT2_F, __fsub_rn(c2, c4));
            CHX(i0, 0, k) = __fadd_rn(tr1, c1);
            CHX(i0, 2, k) = __fsub_rn(c1, tr1);
            CHX(0, 1, k)  = __fsub_rn(ti1, c3);
            CHX(0, 3, k)  = __fadd_rn(ti1, c3);
        }
    }
#undef CCX
#undef CHX
}

// 8 frames per block (one warp each) + fused IF output for warps 1..7.
__global__ __launch_bounds__(256) void fft_phase_out_kernel(
        const float* __restrict__ wav, float* __restrict__ out) {
    __shared__ float SA[8][512];
    __shared__ float SB[8][512];
    __shared__ float PH[8][N_BINS];
    const int warp = threadIdx.x >> 5;
    const int lane = threadIdx.x & 31;
    const int fb   = blockIdx.x * 8 + warp;
    const int frame = fb % N_FRAMES;
    const int b     = fb / N_FRAMES;
    float* A = SA[warp];
    float* B = SB[warp];

    const float* wv = wav + (size_t)b * T_LEN;
    const int base  = frame * HOPX - PADX;
    for (int t = lane; t < 512; t += 32) {
        int i0 = base + t;
        int j0 = (i0 < 0) ? -i0 : ((i0 >= T_LEN) ? 2 * (T_LEN - 1) - i0 : i0);
        A[t] = __fmul_rn(wv[j0], g_win[t]);
    }
    __syncwarp();

    for (int k = lane; k < 128; k += 32) {
        float x0 = A[k], x1 = A[k + 128], x2 = A[k + 256], x3 = A[k + 384];
        float tr1 = __fadd_rn(x1, x3);
        float tr2 = __fadd_rn(x0, x2);
        B[4 * k]     = __fadd_rn(tr1, tr2);
        B[4 * k + 3] = __fsub_rn(tr2, tr1);
        B[4 * k + 1] = __fsub_rn(x0, x2);
        B[4 * k + 2] = __fsub_rn(x3, x1);
    }
    __syncwarp();
    radf4_warp(B, A, 4, 32, lane);  __syncwarp();
    radf4_warp(A, B, 16, 8, lane);  __syncwarp();
    radf4_warp(B, A, 64, 2, lane);  __syncwarp();
    for (int m = lane; m < 128; m += 32) {
        if (m == 0) {
            B[0]   = __fadd_rn(A[0], A[256]);
            B[511] = __fsub_rn(A[0], A[256]);
            B[256] = -A[511];
            B[255] = A[255];
        } else {
            float2 w = g_tw[m];
            float xr = A[2 * m - 1 + 256], xi = A[2 * m + 256];
            float tr2 = __fadd_rn(__fmul_rn(w.x, xr), __fmul_rn(w.y, xi));
            float ti2 = __fsub_rn(__fmul_rn(w.x, xi), __fmul_rn(w.y, xr));
            float ar = A[2 * m - 1], ai = A[2 * m];
            B[2 * m]       = __fadd_rn(ai, ti2);
            B[512 - 2 * m] = __fsub_rn(ti2, ai);
            B[2 * m - 1]   = __fadd_rn(ar, tr2);
            B[511 - 2 * m] = __fsub_rn(ar, tr2);
        }
    }
    __syncwarp();

    for (int k = lane; k < N_BINS; k += 32) {
        float re, im;
        if (k == 0)        { re = B[0];         im = 0.0f; }
        else if (k == 256) { re = B[511];       im = 0.0f; }
        else               { re = B[2 * k - 1]; im = B[2 * k]; }
        float ph = atan2_df(im, re);
        PH[warp][k] = ph;
        if (warp == 0 || warp == 7)              // block-boundary phases
            g_phase[(size_t)fb * N_BINS + k] = ph;
    }
    __syncthreads();

    float* op = out + (size_t)fb * N_BINS;
    if (frame == 0) {                            // first frame of a batch
        for (int k = lane; k < N_BINS; k += 32)
            op[k] = __fdiv_rn(PH[warp][k], PI_F);
    } else if (warp > 0) {                       // predecessor is in-block
        for (int k = lane; k < N_BINS; k += 32) {
            float dd = __fsub_rn(PH[warp][k], PH[warp - 1][k]);
            op[k] = __fdiv_rn(ddmod_of(dd), PI_F);
        }
    }                                            // warp==0,frame!=0: boundary
}

// Block-boundary frames (fb % 8 == 0, frame != 0): read spilled phases.
__global__ __launch_bounds__(256) void boundary_out_kernel(float* __restrict__ out) {
    int i = blockIdx.x * blockDim.x + threadIdx.x;
    if (i >= (N_FB / 8) * N_BINS) return;
    int Bk = i / N_BINS;
    int k  = i % N_BINS;
    int fb = 8 * Bk;
    if (fb % N_FRAMES == 0) return;              // frame 0: already written
    float dd = __fsub_rn(g_phase[(size_t)fb * N_BINS + k],
                         g_phase[(size_t)(fb - 1) * N_BINS + k]);
    out[(size_t)fb * N_BINS + k] = __fdiv_rn(ddmod_of(dd), PI_F);
}

// Window from HOST glibc cosf (the libm XLA:CPU called). Static: graph-safe.
static float h_win[512];

extern "C" void kernel_launch(void* const* d_in, const int* in_sizes, int n_in,
                              void* d_out, int out_size) {
    const float* wav = (const float*)d_in[0];
    float* out = (float*)d_out;
    (void)in_sizes; (void)n_in; (void)out_size;

    {
        const unsigned int two_pi_bits = 0x40C90FDBu;
        float two_pi;
        memcpy(&two_pi, &two_pi_bits, 4);
        volatile int vi = 0;                 // defeat MPFR constant folding
        for (int n = 0; n < 512; ++n) {
            int i = vi;
            float a  = two_pi * (float)i;
            float th = a / 512.0f;
            float c  = cosf(th);
            h_win[n] = 0.5f - 0.5f * c;
            vi = vi + 1;
        }
        cudaMemcpyToSymbolAsync(g_win, h_win, 512 * sizeof(float), 0,
                                cudaMemcpyHostToDevice, 0);
    }

    build_tables_kernel<<<1, 256>>>();
    fft_phase_out_kernel<<<N_FB / 8, 256>>>(wav, out);
    boundary_out_kernel<<<((N_FB / 8) * N_BINS + 255) / 256, 256>>>(out);
}